// round 12
// baseline (speedup 1.0000x reference)
#include <cuda_runtime.h>

#define H  2048
#define S  8192
#define EB 256               // blocks; all resident (2/SM, 128 regs -> exactly fits RF)

// Scratch (no allocs allowed). g_u starts zero (static init); blocks 0..7
// re-zero it after the final barrier each invocation, so "g_u == 0 on entry"
// holds for the correctness run, the capture, and every graph replay.
__device__ float    g_u[H];
__device__ float    g_mb[EB];
__device__ float    g_zb[EB];
__device__ unsigned g_count = 0;   // barrier arrival counter (self-resetting)
__device__ unsigned g_gen   = 0;   // barrier generation (monotonic across replays)

// Grid barrier across EB=256 blocks (all resident; geometry proven in R10).
// Monotonic generation counter -> safe across repeated use & graph replays.
__device__ __forceinline__ void grid_barrier() {
    __syncthreads();
    __threadfence();
    if (threadIdx.x == 0) {
        unsigned gen0 = *(volatile unsigned*)&g_gen;
        if (atomicAdd(&g_count, 1u) == EB - 1) {
            g_count = 0;
            __threadfence();
            atomicAdd(&g_gen, 1u);         // release
        } else {
            while (*(volatile unsigned*)&g_gen == gen0) { }
        }
        __threadfence();                   // acquire
    }
    __syncthreads();
}

// ---------------------------------------------------------------------------
// Single fused kernel.
// Phase 0 (GEMV): block b owns i-rows [8b, 8b+8); thread t accumulates 8
//   columns (t + 256*jg). 64 independent W loads in flight; perfectly
//   balanced across blocks. atomicAdd partials into pre-zeroed g_u.
// Barrier 1.
// Phase A (R10-proven): lane caches full u (16 float4 = 64 regs); each warp
//   streams 4 enc rows, 16 independent LDG.128 per row; energies -> smem;
//   block emits (m_b, z_b).
// Barrier 2.
// Phase B: every block redundantly reduces 256 (m,z) pairs (L2-hot) to
//   (M, 1/Z); normalizes its OWN 32 energies from smem. Blocks 0..7 re-zero
//   g_u (all reads completed before barrier 2).
// ---------------------------------------------------------------------------
#define RPW 4

__global__ __launch_bounds__(256, 2)
void fused_attn(const float* __restrict__ hidden,
                const float* __restrict__ enc,
                const float* __restrict__ W,
                float* __restrict__ out) {
    __shared__ float sE[32];           // 8 warps * 4 rows
    __shared__ float sM, sInvZ;

    const int tid  = threadIdx.x;
    const int wid  = tid >> 5;         // 0..7
    const int lane = tid & 31;

    // ---- Phase 0: u[j] = sum_i h[i] * W[i,j] ----
    {
        const int i0 = blockIdx.x * 8;
        float acc[8] = {0.f, 0.f, 0.f, 0.f, 0.f, 0.f, 0.f, 0.f};
#pragma unroll
        for (int r = 0; r < 8; ++r) {
            const float hv = __ldg(hidden + i0 + r);
            const float* Wrow = W + (size_t)(i0 + r) * H;
#pragma unroll
            for (int jg = 0; jg < 8; ++jg)
                acc[jg] = fmaf(hv, Wrow[jg * 256 + tid], acc[jg]);
        }
#pragma unroll
        for (int jg = 0; jg < 8; ++jg)
            atomicAdd(&g_u[jg * 256 + tid], acc[jg]);
    }

    grid_barrier();   // g_u complete

    // ---- Phase A: u register-resident; stream 4 enc rows per warp ----
    const float4* uv = reinterpret_cast<const float4*>(g_u);
    float4 u[16];
#pragma unroll
    for (int k = 0; k < 16; ++k)
        u[k] = uv[lane + k * 32];

    const int s0 = (blockIdx.x * 8 + wid) * RPW;

#pragma unroll
    for (int r = 0; r < RPW; ++r) {
        const float4* row =
            reinterpret_cast<const float4*>(enc + (size_t)(s0 + r) * H);
        float acc = 0.0f;
#pragma unroll
        for (int k = 0; k < 16; ++k) {
            float4 v = row[lane + k * 32];
            acc = fmaf(v.x, u[k].x, acc);
            acc = fmaf(v.y, u[k].y, acc);
            acc = fmaf(v.z, u[k].z, acc);
            acc = fmaf(v.w, u[k].w, acc);
        }
#pragma unroll
        for (int off = 16; off; off >>= 1)
            acc += __shfl_xor_sync(0xFFFFFFFFu, acc, off);
        if (lane == 0) sE[wid * RPW + r] = acc;
    }
    __syncthreads();

    // Block-local (m, z) over this block's 32 energies (warp 0).
    if (wid == 0) {
        float e = sE[lane];
        float m = e;
#pragma unroll
        for (int off = 16; off; off >>= 1)
            m = fmaxf(m, __shfl_xor_sync(0xFFFFFFFFu, m, off));
        float z = __expf(e - m);
#pragma unroll
        for (int off = 16; off; off >>= 1)
            z += __shfl_xor_sync(0xFFFFFFFFu, z, off);
        if (lane == 0) { g_mb[blockIdx.x] = m; g_zb[blockIdx.x] = z; }
    }

    grid_barrier();   // all (m_b, z_b) visible; all g_u reads complete

    // ---- Phase B: global (M, 1/Z), redundant per block ----
    if (tid < 32) {
        float m = -1e30f;
#pragma unroll
        for (int i = 0; i < EB / 32; ++i)
            m = fmaxf(m, g_mb[lane + i * 32]);
#pragma unroll
        for (int off = 16; off; off >>= 1)
            m = fmaxf(m, __shfl_xor_sync(0xFFFFFFFFu, m, off));
        float z = 0.0f;
#pragma unroll
        for (int i = 0; i < EB / 32; ++i)
            z += g_zb[lane + i * 32] * __expf(g_mb[lane + i * 32] - m);
#pragma unroll
        for (int off = 16; off; off >>= 1)
            z += __shfl_xor_sync(0xFFFFFFFFu, z, off);
        if (lane == 0) { sM = m; sInvZ = 1.0f / z; }
    }
    __syncthreads();

    // Normalize this block's 32 energies (still in smem) -> out.
    if (tid < 32)
        out[blockIdx.x * 32 + tid] = __expf(sE[tid] - sM) * sInvZ;

    // Restore g_u == 0 invariant.
    if (blockIdx.x < 8)
        g_u[blockIdx.x * 256 + tid] = 0.0f;
}

// ---------------------------------------------------------------------------
// Launch. Inputs: hidden[2048], encoder_outputs[8192*2048], W[2048*2048],
// b[2048] (zero + softmax-invariant -> ignored). Output: 8192 floats.
// ---------------------------------------------------------------------------
extern "C" void kernel_launch(void* const* d_in, const int* in_sizes, int n_in,
                              void* d_out, int out_size) {
    const float* hidden = (const float*)d_in[0];
    const float* enc    = (const float*)d_in[1];
    const float* W      = (const float*)d_in[2];
    float* out          = (float*)d_out;

    fused_attn<<<EB, 256>>>(hidden, enc, W, out);
}

// round 13
// speedup vs baseline: 1.1065x; 1.1065x over previous
#include <cuda_runtime.h>

#define H 2048
#define S 8192
#define EB 256               // k_energy blocks (all resident: 2/SM, 128 regs)

// Scratch (no allocs allowed). g_u starts zero (static init); k_energy
// re-zeros it each invocation after the grid barrier, so "g_u == 0 on entry"
// holds for the correctness run, the capture, and every graph replay.
__device__ float    g_u[H];
__device__ float    g_mb[EB];
__device__ float    g_zb[EB];
__device__ unsigned g_count = 0;   // barrier arrival counter (self-resetting)
__device__ unsigned g_gen   = 0;   // barrier generation (monotonic across replays)

// ---------------------------------------------------------------------------
// Kernel 1: u[j] += sum over an 8-row i-chunk of h[i] * W[i, j]
// Grid (H/256, 256) = 2048 blocks (~14/SM). Fully unrolled 8-row loop,
// scalar coalesced loads -> maximal chip-wide loads in flight.
// ---------------------------------------------------------------------------
#define ICHUNKS 256
#define IROWS   (H / ICHUNKS)     // 8

__global__ void k_compute_u(const float* __restrict__ h,
                            const float* __restrict__ W) {
    const int j  = blockIdx.x * blockDim.x + threadIdx.x;
    const int i0 = blockIdx.y * IROWS;

    float acc = 0.0f;
#pragma unroll
    for (int r = 0; r < IROWS; ++r) {
        const int i = i0 + r;
        acc = fmaf(__ldg(h + i), W[(size_t)i * H + j], acc);
    }
    atomicAdd(&g_u[j], acc);
}

// ---------------------------------------------------------------------------
// Grid barrier across EB=256 blocks (all resident; geometry proven R10).
// Monotonic generation counter -> graph-replay safe.
// ---------------------------------------------------------------------------
__device__ __forceinline__ void grid_barrier() {
    __syncthreads();
    __threadfence();
    if (threadIdx.x == 0) {
        unsigned gen0 = *(volatile unsigned*)&g_gen;
        if (atomicAdd(&g_count, 1u) == EB - 1) {
            g_count = 0;
            __threadfence();
            atomicAdd(&g_gen, 1u);         // release
        } else {
            while (*(volatile unsigned*)&g_gen == gen0) { }
        }
        __threadfence();                   // acquire
    }
    __syncthreads();
}

// ---------------------------------------------------------------------------
// Kernel 2: energies + softmax, fused via one balanced grid barrier (R10).
// Phase A: u register-resident per warp (lane caches u4[lane+32k], 64 regs);
// each warp streams 4 enc rows (16 independent LDG.128 per row); energies
// land in smem; block emits (m_b, z_b).
// Barrier. Phase B: every block redundantly reduces the 256 (m,z) pairs
// (L2-hot) to (M, 1/Z) and normalizes its OWN 32 energies from smem.
// Blocks 0..7 re-zero g_u (all u reads complete before the barrier).
// ---------------------------------------------------------------------------
#define RPW 4

__global__ __launch_bounds__(256, 2)
void k_energy(const float* __restrict__ enc, float* __restrict__ out) {
    __shared__ float sE[32];           // 8 warps * 4 rows
    __shared__ float sM, sInvZ;

    const int tid  = threadIdx.x;
    const int wid  = tid >> 5;         // 0..7
    const int lane = tid & 31;

    // ---- Phase A: cache u in registers (L2-hot after k_compute_u) ----
    const float4* uv = reinterpret_cast<const float4*>(g_u);
    float4 u[16];
#pragma unroll
    for (int k = 0; k < 16; ++k)
        u[k] = uv[lane + k * 32];

    const int s0 = (blockIdx.x * 8 + wid) * RPW;

#pragma unroll
    for (int r = 0; r < RPW; ++r) {
        const float4* row =
            reinterpret_cast<const float4*>(enc + (size_t)(s0 + r) * H);
        float acc = 0.0f;
#pragma unroll
        for (int k = 0; k < 16; ++k) {
            float4 v = row[lane + k * 32];
            acc = fmaf(v.x, u[k].x, acc);
            acc = fmaf(v.y, u[k].y, acc);
            acc = fmaf(v.z, u[k].z, acc);
            acc = fmaf(v.w, u[k].w, acc);
        }
#pragma unroll
        for (int off = 16; off; off >>= 1)
            acc += __shfl_xor_sync(0xFFFFFFFFu, acc, off);
        if (lane == 0) sE[wid * RPW + r] = acc;
    }
    __syncthreads();

    // Block-local (m, z) over this block's 32 energies (warp 0).
    if (wid == 0) {
        float e = sE[lane];
        float m = e;
#pragma unroll
        for (int off = 16; off; off >>= 1)
            m = fmaxf(m, __shfl_xor_sync(0xFFFFFFFFu, m, off));
        float z = __expf(e - m);
#pragma unroll
        for (int off = 16; off; off >>= 1)
            z += __shfl_xor_sync(0xFFFFFFFFu, z, off);
        if (lane == 0) { g_mb[blockIdx.x] = m; g_zb[blockIdx.x] = z; }
    }

    grid_barrier();   // all (m_b, z_b) visible; all u reads complete

    // ---- Phase B: global (M, 1/Z), redundant per block ----
    if (tid < 32) {
        float m = -1e30f;
#pragma unroll
        for (int i = 0; i < EB / 32; ++i)
            m = fmaxf(m, g_mb[lane + i * 32]);
#pragma unroll
        for (int off = 16; off; off >>= 1)
            m = fmaxf(m, __shfl_xor_sync(0xFFFFFFFFu, m, off));
        float z = 0.0f;
#pragma unroll
        for (int i = 0; i < EB / 32; ++i)
            z += g_zb[lane + i * 32] * __expf(g_mb[lane + i * 32] - m);
#pragma unroll
        for (int off = 16; off; off >>= 1)
            z += __shfl_xor_sync(0xFFFFFFFFu, z, off);
        if (lane == 0) { sM = m; sInvZ = 1.0f / z; }
    }
    __syncthreads();

    // Normalize this block's 32 energies (still in smem) -> out.
    if (tid < 32)
        out[blockIdx.x * 32 + tid] = __expf(sE[tid] - sM) * sInvZ;

    // Restore g_u == 0 invariant (u consumed before the barrier).
    if (blockIdx.x < 8)
        g_u[blockIdx.x * 256 + tid] = 0.0f;
}

// ---------------------------------------------------------------------------
// Launch. Inputs: hidden[2048], encoder_outputs[8192*2048], W[2048*2048],
// b[2048] (zero + softmax-invariant -> ignored). Output: 8192 floats.
// ---------------------------------------------------------------------------
extern "C" void kernel_launch(void* const* d_in, const int* in_sizes, int n_in,
                              void* d_out, int out_size) {
    const float* hidden = (const float*)d_in[0];
    const float* enc    = (const float*)d_in[1];
    const float* W      = (const float*)d_in[2];
    float* out          = (float*)d_out;

    dim3 g1(H / 256, ICHUNKS);   // (8, 256) = 2048 blocks
    k_compute_u<<<g1, 256>>>(hidden, W);

    k_energy<<<EB, 256>>>(enc, out);
}

// round 14
// speedup vs baseline: 1.1233x; 1.0152x over previous
#include <cuda_runtime.h>

#define H 2048
#define S 8192
#define EB 256               // k_energy blocks (3/SM via launch_bounds -> all resident)

// Scratch (no allocs allowed). g_u starts zero (static init); k_energy
// re-zeros it each invocation after the grid barrier, so "g_u == 0 on entry"
// holds for the correctness run, the capture, and every graph replay.
__device__ float    g_u[H];
__device__ float    g_mb[EB];
__device__ float    g_zb[EB];
__device__ unsigned g_count = 0;   // barrier arrival counter (self-resetting)
__device__ unsigned g_gen   = 0;   // barrier generation (monotonic across replays)

// ---------------------------------------------------------------------------
// Kernel 1: u[j] += sum over a 16-row i-chunk of h[i] * W[i, j]
// Grid (H/256, 128) = 1024 blocks. Fully unrolled 16-row loop, scalar
// coalesced loads. (Proven R9/R10: 7.2-7.8us cold.)
// ---------------------------------------------------------------------------
#define ICHUNKS 128
#define IROWS   (H / ICHUNKS)     // 16

__global__ void k_compute_u(const float* __restrict__ h,
                            const float* __restrict__ W) {
    const int j  = blockIdx.x * blockDim.x + threadIdx.x;
    const int i0 = blockIdx.y * IROWS;

    float acc = 0.0f;
#pragma unroll
    for (int r = 0; r < IROWS; ++r) {
        const int i = i0 + r;
        acc = fmaf(__ldg(h + i), W[(size_t)i * H + j], acc);
    }
    atomicAdd(&g_u[j], acc);
}

// ---------------------------------------------------------------------------
// Grid barrier across EB=256 blocks (all resident). Monotonic generation
// counter -> graph-replay safe.
// ---------------------------------------------------------------------------
__device__ __forceinline__ void grid_barrier() {
    __syncthreads();
    __threadfence();
    if (threadIdx.x == 0) {
        unsigned gen0 = *(volatile unsigned*)&g_gen;
        if (atomicAdd(&g_count, 1u) == EB - 1) {
            g_count = 0;
            __threadfence();
            atomicAdd(&g_gen, 1u);         // release
        } else {
            while (*(volatile unsigned*)&g_gen == gen0) { }
        }
        __threadfence();                   // acquire
    }
    __syncthreads();
}

// ---------------------------------------------------------------------------
// Kernel 2: energies + softmax, fused via one balanced grid barrier.
// Phase A: u staged once per block into SMEM (8KB) -> frees 64 regs vs the
// register-cache version, so all 16 enc LDG.128 per row stay in flight AND
// 3 blocks/SM (24 warps) are resident. Each warp streams 4 enc rows.
// Barrier. Phase B: every block redundantly reduces 256 (m,z) pairs to
// (M, 1/Z), normalizes its OWN 32 energies from smem. Blocks 0..7 re-zero
// g_u (read completed before the barrier).
// ---------------------------------------------------------------------------
#define RPW 4

__global__ __launch_bounds__(256, 3)
void k_energy(const float* __restrict__ enc, float* __restrict__ out) {
    __shared__ float4 sU[H / 4];       // 8 KB staged u
    __shared__ float  sE[32];          // 8 warps * 4 rows
    __shared__ float  sM, sInvZ;

    const int tid  = threadIdx.x;
    const int wid  = tid >> 5;         // 0..7
    const int lane = tid & 31;

    // ---- Stage u into smem (512 float4, 256 threads -> 2 each) ----
    {
        const float4* uv = reinterpret_cast<const float4*>(g_u);
        sU[tid]       = uv[tid];
        sU[tid + 256] = uv[tid + 256];
    }
    __syncthreads();

    const int s0 = (blockIdx.x * 8 + wid) * RPW;

#pragma unroll
    for (int r = 0; r < RPW; ++r) {
        const float4* row =
            reinterpret_cast<const float4*>(enc + (size_t)(s0 + r) * H);
        float acc = 0.0f;
#pragma unroll
        for (int k = 0; k < 16; ++k) {
            float4 v = row[lane + k * 32];
            float4 u = sU [lane + k * 32];
            acc = fmaf(v.x, u.x, acc);
            acc = fmaf(v.y, u.y, acc);
            acc = fmaf(v.z, u.z, acc);
            acc = fmaf(v.w, u.w, acc);
        }
#pragma unroll
        for (int off = 16; off; off >>= 1)
            acc += __shfl_xor_sync(0xFFFFFFFFu, acc, off);
        if (lane == 0) sE[wid * RPW + r] = acc;
    }
    __syncthreads();

    // Block-local (m, z) over this block's 32 energies (warp 0).
    if (wid == 0) {
        float e = sE[lane];
        float m = e;
#pragma unroll
        for (int off = 16; off; off >>= 1)
            m = fmaxf(m, __shfl_xor_sync(0xFFFFFFFFu, m, off));
        float z = __expf(e - m);
#pragma unroll
        for (int off = 16; off; off >>= 1)
            z += __shfl_xor_sync(0xFFFFFFFFu, z, off);
        if (lane == 0) { g_mb[blockIdx.x] = m; g_zb[blockIdx.x] = z; }
    }

    grid_barrier();   // all (m_b, z_b) visible; all g_u reads complete

    // ---- Phase B: global (M, 1/Z), redundant per block ----
    if (tid < 32) {
        float m = -1e30f;
#pragma unroll
        for (int i = 0; i < EB / 32; ++i)
            m = fmaxf(m, g_mb[lane + i * 32]);
#pragma unroll
        for (int off = 16; off; off >>= 1)
            m = fmaxf(m, __shfl_xor_sync(0xFFFFFFFFu, m, off));
        float z = 0.0f;
#pragma unroll
        for (int i = 0; i < EB / 32; ++i)
            z += g_zb[lane + i * 32] * __expf(g_mb[lane + i * 32] - m);
#pragma unroll
        for (int off = 16; off; off >>= 1)
            z += __shfl_xor_sync(0xFFFFFFFFu, z, off);
        if (lane == 0) { sM = m; sInvZ = 1.0f / z; }
    }
    __syncthreads();

    // Normalize this block's 32 energies (still in smem) -> out.
    if (tid < 32)
        out[blockIdx.x * 32 + tid] = __expf(sE[tid] - sM) * sInvZ;

    // Restore g_u == 0 invariant (u consumed before the barrier).
    if (blockIdx.x < 8)
        g_u[blockIdx.x * 256 + tid] = 0.0f;
}

// ---------------------------------------------------------------------------
// Launch. Inputs: hidden[2048], encoder_outputs[8192*2048], W[2048*2048],
// b[2048] (zero + softmax-invariant -> ignored). Output: 8192 floats.
// ---------------------------------------------------------------------------
extern "C" void kernel_launch(void* const* d_in, const int* in_sizes, int n_in,
                              void* d_out, int out_size) {
    const float* hidden = (const float*)d_in[0];
    const float* enc    = (const float*)d_in[1];
    const float* W      = (const float*)d_in[2];
    float* out          = (float*)d_out;

    dim3 g1(H / 256, ICHUNKS);   // (8, 128) = 1024 blocks
    k_compute_u<<<g1, 256>>>(hidden, W);

    k_energy<<<EB, 256>>>(enc, out);
}